// round 3
// baseline (speedup 1.0000x reference)
#include <cuda_runtime.h>
#include <math.h>

// Problem constants
#define BB 2
#define NN 1024
#define CSD 384
#define HH 12
#define CC 16
#define PQN 4
#define PVN 8
#define NPAD 1026        // N + 2*PAD
#define PROW 512         // num_pool
#define TT 1538          // NPAD + PROW
#define HC 192           // H*C
#define HPQ3 144         // H*PQ*3
#define HPV3 288         // H*PV*3
#define OCW 576          // HC + HPV3 + H*PV
#define ATTS 8           // split-KV factor
#define ACHUNK ((TT + ATTS - 1) / ATTS)   // 193

#define C1 0.176776695f       // w_l * (1/sqrt(C))
#define WC_HALF 0.117851130f  // w_c/2

// Scratch (device globals)
__device__ float g_s_all[BB*TT*CSD];
__device__ float g_t_all[BB*TT*3];
__device__ float g_r_all[BB*TT*9];
__device__ float g_k  [BB*TT*HC];
__device__ float g_v  [BB*TT*HC];
__device__ float g_kp [BB*TT*HPQ3];
__device__ float g_vp [BB*TT*HPV3];
__device__ float g_sk [BB*TT*HH];
__device__ float g_q  [BB*PROW*HC];
__device__ float g_qp [BB*PROW*HPQ3];
__device__ float g_oc [BB*PROW*OCW];
__device__ float g_wfold[6*OCW];

#define NPART (BB*PROW*HH*ATTS)
__device__ float g_pm[NPART];
__device__ float g_pl[NPART];
__device__ float g_po[NPART*CC];
__device__ float g_pg[NPART*PVN*3];

__device__ __forceinline__ int clampsrc(int e) {
    int v = e - 1;
    return v < 0 ? 0 : (v > NN - 1 ? NN - 1 : v);
}

// ---------------------------------------------------------------------------
// Fused pooling prep: s_all (first S_TOT ids) then t/r (next 12*BB*TT ids)
// ---------------------------------------------------------------------------
#define S_TOT (BB*TT*CSD)
#define TR_TOT (BB*TT*12)
__global__ void prep_all_kernel(const float* __restrict__ s,
                                const float* __restrict__ trans,
                                const float* __restrict__ rots) {
    int idx = blockIdx.x * blockDim.x + threadIdx.x;
    if (idx < S_TOT) {
        int c = idx % CSD;
        int bt = idx / CSD;
        int t = bt % TT;
        int b = bt / TT;
        float val;
        if (t < NPAD) {
            val = s[(b * NN + clampsrc(t)) * CSD + c];
        } else {
            int p = t - NPAD;
            val = (s[(b * NN + clampsrc(2 * p    )) * CSD + c]
                 + s[(b * NN + clampsrc(2 * p + 1)) * CSD + c]
                 + s[(b * NN + clampsrc(2 * p + 2)) * CSD + c]) * (1.f / 3.f);
        }
        g_s_all[idx] = val;
        return;
    }
    int k = idx - S_TOT;
    if (k >= TR_TOT) return;
    int d = k % 12;
    int bt = k / 12;
    int t = bt % TT;
    int b = bt / TT;
    if (d < 3) {
        float val;
        if (t < NPAD) {
            val = trans[(b * NN + clampsrc(t)) * 3 + d];
        } else {
            int p = t - NPAD;
            val = (trans[(b * NN + clampsrc(2 * p    )) * 3 + d]
                 + trans[(b * NN + clampsrc(2 * p + 1)) * 3 + d]
                 + trans[(b * NN + clampsrc(2 * p + 2)) * 3 + d]) * (1.f / 3.f);
        }
        g_t_all[(b * TT + t) * 3 + d] = val;
    } else {
        int r = d - 3;
        float val;
        if (t < NPAD) {
            val = rots[(b * NN + clampsrc(t)) * 9 + r];
        } else {
            int p = t - NPAD;
            val = (rots[(b * NN + clampsrc(2 * p    )) * 9 + r]
                 + rots[(b * NN + clampsrc(2 * p + 1)) * 9 + r]
                 + rots[(b * NN + clampsrc(2 * p + 2)) * 9 + r]) * (1.f / 3.f);
        }
        g_r_all[(b * TT + t) * 9 + r] = val;
    }
}

// ---------------------------------------------------------------------------
// Fused multi-task SGEMM, tile 128x64, BK=16, 256 threads, 8x4 per thread.
// ---------------------------------------------------------------------------
#define NTASK 8
struct GemmTask {
    const float* A;
    const float* B;
    float* C;
    int M, N, K, gx;
};
struct TaskPack {
    GemmTask t[NTASK];
    int ofs[NTASK + 1];
};

#define GBM 128
#define GBN 64
#define GBK 16
__global__ void mgemm_kernel(TaskPack P) {
    int bid = blockIdx.x;
    int ti = 0;
#pragma unroll
    for (int x = 0; x < NTASK - 1; x++)
        if (bid >= P.ofs[x + 1]) ti = x + 1;
    GemmTask tk = P.t[ti];
    int lb = bid - P.ofs[ti];
    int bx = lb % tk.gx, by = lb / tk.gx;

    __shared__ __align__(16) float As[GBK][GBM];
    __shared__ __align__(16) float Bs[GBK][GBN];
    int tid = threadIdx.x;
    int tx = tid % 16, ty = tid / 16;   // tx: 16 cols x4, ty: 16 rows x8
    int row0 = by * GBM;
    int col0 = bx * GBN;
    const float* A = tk.A;
    const float* Bm = tk.B;
    int M = tk.M, Nn = tk.N, K = tk.K;

    float acc[8][4];
#pragma unroll
    for (int i = 0; i < 8; i++)
#pragma unroll
        for (int j = 0; j < 4; j++) acc[i][j] = 0.f;

    for (int k0 = 0; k0 < K; k0 += GBK) {
        // As: 128*16 = 2048 elems, 8 per thread
#pragma unroll
        for (int x = 0; x < (GBM * GBK) / 256; x++) {
            int li = tid + x * 256;
            int m = li / GBK, kk = li % GBK;
            int gm = row0 + m;
            As[kk][m] = (gm < M) ? A[(long)gm * K + k0 + kk] : 0.f;
        }
        // Bs: 16*64 = 1024 elems, 4 per thread
#pragma unroll
        for (int x = 0; x < (GBK * GBN) / 256; x++) {
            int li = tid + x * 256;
            int kk = li / GBN, n = li % GBN;
            int gn = col0 + n;
            Bs[kk][n] = (gn < Nn) ? Bm[(long)(k0 + kk) * Nn + gn] : 0.f;
        }
        __syncthreads();
#pragma unroll
        for (int kk = 0; kk < GBK; kk++) {
            float a[8], bvals[4];
#pragma unroll
            for (int i = 0; i < 8; i++) a[i] = As[kk][ty * 8 + i];
#pragma unroll
            for (int j = 0; j < 4; j++) bvals[j] = Bs[kk][tx * 4 + j];
#pragma unroll
            for (int i = 0; i < 8; i++)
#pragma unroll
                for (int j = 0; j < 4; j++) acc[i][j] += a[i] * bvals[j];
        }
        __syncthreads();
    }
#pragma unroll
    for (int i = 0; i < 8; i++) {
        int gm = row0 + ty * 8 + i;
        if (gm >= M) continue;
#pragma unroll
        for (int j = 0; j < 4; j++) {
            int gn = col0 + tx * 4 + j;
            if (gn < Nn) tk.C[(long)gm * Nn + gn] = acc[i][j];
        }
    }
}

// ---------------------------------------------------------------------------
// Weight fold: wfold[6][OCW] = (wout @ wupd)^T. One warp per OCW-row k.
// ---------------------------------------------------------------------------
__global__ void fold_w_kernel(const float* __restrict__ wout,
                              const float* __restrict__ wupd) {
    int gw = (blockIdx.x * blockDim.x + threadIdx.x) >> 5;
    int lane = threadIdx.x & 31;
    if (gw >= OCW) return;
    const float* wr = wout + (long)gw * CSD;
    float acc[6] = {0, 0, 0, 0, 0, 0};
    for (int m = lane; m < CSD; m += 32) {
        float w = wr[m];
#pragma unroll
        for (int j = 0; j < 6; j++) acc[j] += w * __ldg(&wupd[m * 6 + j]);
    }
#pragma unroll
    for (int off = 16; off > 0; off >>= 1)
#pragma unroll
        for (int j = 0; j < 6; j++)
            acc[j] += __shfl_down_sync(0xffffffffu, acc[j], off);
    if (lane == 0) {
#pragma unroll
        for (int j = 0; j < 6; j++) g_wfold[j * OCW + gw] = acc[j];
    }
}

// ---------------------------------------------------------------------------
// Point transforms: fused kv (all rows) + q (pooled rows).
// ids [0, BB*TT*HH): kv; [BB*TT*HH, +BB*PROW*HH): q
// ---------------------------------------------------------------------------
#define KV_TOT (BB*TT*HH)
#define Q_TOT (BB*PROW*HH)
__global__ void transform_all_kernel() {
    int idx = blockIdx.x * blockDim.x + threadIdx.x;
    if (idx < KV_TOT) {
        int h = idx % HH;
        int rt = idx / HH;
        float R[9], tr[3];
#pragma unroll
        for (int r = 0; r < 9; r++) R[r] = g_r_all[rt * 9 + r];
#pragma unroll
        for (int r = 0; r < 3; r++) tr[r] = g_t_all[rt * 3 + r];

        float sk = 0.f;
        int kb = rt * HPQ3 + h * PQN * 3;
#pragma unroll
        for (int p = 0; p < PQN; p++) {
            float lx = g_kp[kb + p * 3 + 0];
            float ly = g_kp[kb + p * 3 + 1];
            float lz = g_kp[kb + p * 3 + 2];
            float gx = R[0] * lx + R[1] * ly + R[2] * lz + tr[0];
            float gy = R[3] * lx + R[4] * ly + R[5] * lz + tr[1];
            float gz = R[6] * lx + R[7] * ly + R[8] * lz + tr[2];
            g_kp[kb + p * 3 + 0] = gx;
            g_kp[kb + p * 3 + 1] = gy;
            g_kp[kb + p * 3 + 2] = gz;
            sk += gx * gx + gy * gy + gz * gz;
        }
        g_sk[rt * HH + h] = sk;

        int vb = rt * HPV3 + h * PVN * 3;
#pragma unroll
        for (int p = 0; p < PVN; p++) {
            float lx = g_vp[vb + p * 3 + 0];
            float ly = g_vp[vb + p * 3 + 1];
            float lz = g_vp[vb + p * 3 + 2];
            float gx = R[0] * lx + R[1] * ly + R[2] * lz + tr[0];
            float gy = R[3] * lx + R[4] * ly + R[5] * lz + tr[1];
            float gz = R[6] * lx + R[7] * ly + R[8] * lz + tr[2];
            g_vp[vb + p * 3 + 0] = gx;
            g_vp[vb + p * 3 + 1] = gy;
            g_vp[vb + p * 3 + 2] = gz;
        }
        return;
    }
    int k = idx - KV_TOT;
    if (k >= Q_TOT) return;
    int h = k % HH;
    int row = k / HH;
    int b = row / PROW, i = row % PROW;
    int ridx = b * TT + NPAD + i;
    float R[9], tr[3];
#pragma unroll
    for (int r = 0; r < 9; r++) R[r] = g_r_all[ridx * 9 + r];
#pragma unroll
    for (int r = 0; r < 3; r++) tr[r] = g_t_all[ridx * 3 + r];
    int qb = row * HPQ3 + h * PQN * 3;
#pragma unroll
    for (int p = 0; p < PQN; p++) {
        float lx = g_qp[qb + p * 3 + 0];
        float ly = g_qp[qb + p * 3 + 1];
        float lz = g_qp[qb + p * 3 + 2];
        float gx = R[0] * lx + R[1] * ly + R[2] * lz + tr[0];
        float gy = R[3] * lx + R[4] * ly + R[5] * lz + tr[1];
        float gz = R[6] * lx + R[7] * ly + R[8] * lz + tr[2];
        g_qp[qb + p * 3 + 0] = gx;
        g_qp[qb + p * 3 + 1] = gy;
        g_qp[qb + p * 3 + 2] = gz;
    }
}

// ---------------------------------------------------------------------------
// Split-KV attention. grid (B*H, PROW/ATH, ATTS), block ATH threads.
// ---------------------------------------------------------------------------
#define TJ 32
#define ATH 128
__global__ void attn_split_kernel(const float* __restrict__ gamma) {
    int bh = blockIdx.x;
    int b = bh / HH, h = bh % HH;
    int i = blockIdx.y * ATH + threadIdx.x;
    int sp = blockIdx.z;
    int tid = threadIdx.x;

    int j_begin = sp * ACHUNK;
    int j_end = j_begin + ACHUNK;
    if (j_end > TT) j_end = TT;

    __shared__ __align__(16) float k_s [TJ][CC];
    __shared__ __align__(16) float v_s [TJ][CC];
    __shared__ __align__(16) float kg_s[TJ][PQN * 3];
    __shared__ __align__(16) float vg_s[TJ][PVN * 3];
    __shared__ float sk_s[TJ];

    int qrow = b * PROW + i;
    float q[CC], qg[PQN * 3];
    {
        const float4* q4 = reinterpret_cast<const float4*>(g_q + (long)qrow * HC + h * CC);
#pragma unroll
        for (int c = 0; c < 4; c++) {
            float4 v = q4[c];
            q[c*4+0] = v.x; q[c*4+1] = v.y; q[c*4+2] = v.z; q[c*4+3] = v.w;
        }
        const float4* g4 = reinterpret_cast<const float4*>(g_qp + (long)qrow * HPQ3 + h * PQN * 3);
#pragma unroll
        for (int c = 0; c < 3; c++) {
            float4 v = g4[c];
            qg[c*4+0] = v.x; qg[c*4+1] = v.y; qg[c*4+2] = v.z; qg[c*4+3] = v.w;
        }
    }
    float sq = 0.f;
#pragma unroll
    for (int x = 0; x < PQN * 3; x++) sq += qg[x] * qg[x];

    float gm = gamma[h];
    float gcoef = logf(1.f + __expf(gm)) * WC_HALF;

    float mrun = -1e30f, lrun = 0.f;
    float ao[CC], ag[PVN * 3];
#pragma unroll
    for (int c = 0; c < CC; c++) ao[c] = 0.f;
#pragma unroll
    for (int x = 0; x < PVN * 3; x++) ag[x] = 0.f;

    for (int j0 = j_begin; j0 < j_end; j0 += TJ) {
        __syncthreads();
        for (int x = tid; x < TJ * 4; x += ATH) {
            int j = x >> 2, c4 = x & 3;
            int jj = j0 + j;
            float4 v = (jj < TT)
                ? reinterpret_cast<const float4*>(g_k + ((long)(b * TT + jj) * HC + h * CC))[c4]
                : make_float4(0.f, 0.f, 0.f, 0.f);
            reinterpret_cast<float4*>(&k_s[j][0])[c4] = v;
        }
        for (int x = tid; x < TJ * 4; x += ATH) {
            int j = x >> 2, c4 = x & 3;
            int jj = j0 + j;
            float4 v = (jj < TT)
                ? reinterpret_cast<const float4*>(g_v + ((long)(b * TT + jj) * HC + h * CC))[c4]
                : make_float4(0.f, 0.f, 0.f, 0.f);
            reinterpret_cast<float4*>(&v_s[j][0])[c4] = v;
        }
        for (int x = tid; x < TJ * 3; x += ATH) {
            int j = x / 3, c4 = x % 3;
            int jj = j0 + j;
            float4 v = (jj < TT)
                ? reinterpret_cast<const float4*>(g_kp + ((long)(b * TT + jj) * HPQ3 + h * PQN * 3))[c4]
                : make_float4(0.f, 0.f, 0.f, 0.f);
            reinterpret_cast<float4*>(&kg_s[j][0])[c4] = v;
        }
        for (int x = tid; x < TJ * 6; x += ATH) {
            int j = x / 6, c4 = x % 6;
            int jj = j0 + j;
            float4 v = (jj < TT)
                ? reinterpret_cast<const float4*>(g_vp + ((long)(b * TT + jj) * HPV3 + h * PVN * 3))[c4]
                : make_float4(0.f, 0.f, 0.f, 0.f);
            reinterpret_cast<float4*>(&vg_s[j][0])[c4] = v;
        }
        for (int x = tid; x < TJ; x += ATH) {
            int jj = j0 + x;
            sk_s[x] = (jj < TT) ? g_sk[(long)(b * TT + jj) * HH + h] : 0.f;
        }
        __syncthreads();

        int nv = j_end - j0;
        if (nv > TJ) nv = TJ;

        float logit[TJ];
        float tmax = -1e30f;
#pragma unroll
        for (int jj = 0; jj < TJ; jj++) {
            float qk = 0.f;
            const float4* k4 = reinterpret_cast<const float4*>(&k_s[jj][0]);
#pragma unroll
            for (int c = 0; c < 4; c++) {
                float4 kv = k4[c];
                qk += q[c*4+0] * kv.x + q[c*4+1] * kv.y + q[c*4+2] * kv.z + q[c*4+3] * kv.w;
            }
            float dt = 0.f;
            const float4* g4 = reinterpret_cast<const float4*>(&kg_s[jj][0]);
#pragma unroll
            for (int c = 0; c < 3; c++) {
                float4 kv = g4[c];
                dt += qg[c*4+0] * kv.x + qg[c*4+1] * kv.y + qg[c*4+2] * kv.z + qg[c*4+3] * kv.w;
            }
            float d2 = sq + sk_s[jj] - 2.f * dt;
            float lg = C1 * qk - gcoef * d2;
            logit[jj] = (jj < nv) ? lg : -1e30f;
            tmax = fmaxf(tmax, logit[jj]);
        }
        float mn = fmaxf(mrun, tmax);
        float corr = __expf(mrun - mn);
        lrun *= corr;
#pragma unroll
        for (int c = 0; c < CC; c++) ao[c] *= corr;
#pragma unroll
        for (int x = 0; x < PVN * 3; x++) ag[x] *= corr;
#pragma unroll
        for (int jj = 0; jj < TJ; jj++) {
            float e = __expf(logit[jj] - mn);
            lrun += e;
            const float4* v4 = reinterpret_cast<const float4*>(&v_s[jj][0]);
#pragma unroll
            for (int c = 0; c < 4; c++) {
                float4 vv = v4[c];
                ao[c*4+0] += e * vv.x; ao[c*4+1] += e * vv.y;
                ao[c*4+2] += e * vv.z; ao[c*4+3] += e * vv.w;
            }
            const float4* g4 = reinterpret_cast<const float4*>(&vg_s[jj][0]);
#pragma unroll
            for (int c = 0; c < 6; c++) {
                float4 vv = g4[c];
                ag[c*4+0] += e * vv.x; ag[c*4+1] += e * vv.y;
                ag[c*4+2] += e * vv.z; ag[c*4+3] += e * vv.w;
            }
        }
        mrun = mn;
    }

    int p = (qrow * HH + h) * ATTS + sp;
    g_pm[p] = mrun;
    g_pl[p] = lrun;
#pragma unroll
    for (int c = 0; c < CC; c++) g_po[(long)p * CC + c] = ao[c];
#pragma unroll
    for (int x = 0; x < PVN * 3; x++) g_pg[(long)p * (PVN * 3) + x] = ag[x];
}

// ---------------------------------------------------------------------------
// Combine split partials + build oc rows. One thread per (b,i,h).
// ---------------------------------------------------------------------------
__global__ void combine_oc_kernel() {
    int idx = blockIdx.x * blockDim.x + threadIdx.x;
    if (idx >= BB * PROW * HH) return;
    int h = idx % HH;
    int row = idx / HH;
    int b = row / PROW, i = row % PROW;
    int p0 = idx * ATTS;

    float m = -1e30f;
#pragma unroll
    for (int s = 0; s < ATTS; s++) m = fmaxf(m, g_pm[p0 + s]);
    float L = 0.f;
    float o[CC], g[PVN * 3];
#pragma unroll
    for (int c = 0; c < CC; c++) o[c] = 0.f;
#pragma unroll
    for (int x = 0; x < PVN * 3; x++) g[x] = 0.f;
#pragma unroll
    for (int s = 0; s < ATTS; s++) {
        float w = __expf(g_pm[p0 + s] - m);
        L += g_pl[p0 + s] * w;
        const float* po = g_po + (long)(p0 + s) * CC;
        const float* pg = g_pg + (long)(p0 + s) * (PVN * 3);
#pragma unroll
        for (int c = 0; c < CC; c++) o[c] += w * po[c];
#pragma unroll
        for (int x = 0; x < PVN * 3; x++) g[x] += w * pg[x];
    }
    float inv = 1.f / L;
#pragma unroll
    for (int c = 0; c < CC; c++) o[c] *= inv;
#pragma unroll
    for (int x = 0; x < PVN * 3; x++) g[x] *= inv;

    int ridx = b * TT + NPAD + i;
    float R[9], tr[3];
#pragma unroll
    for (int r = 0; r < 9; r++) R[r] = g_r_all[ridx * 9 + r];
#pragma unroll
    for (int r = 0; r < 3; r++) tr[r] = g_t_all[ridx * 3 + r];

#pragma unroll
    for (int c = 0; c < CC; c++)
        g_oc[(long)row * OCW + h * CC + c] = o[c];

#pragma unroll
    for (int pp = 0; pp < PVN; pp++) {
        float gx = g[pp * 3 + 0] - tr[0];
        float gy = g[pp * 3 + 1] - tr[1];
        float gz = g[pp * 3 + 2] - tr[2];
        float lx = R[0] * gx + R[3] * gy + R[6] * gz;
        float ly = R[1] * gx + R[4] * gy + R[7] * gz;
        float lz = R[2] * gx + R[5] * gy + R[8] * gz;
        g_oc[(long)row * OCW + HC + h * PVN * 3 + pp * 3 + 0] = lx;
        g_oc[(long)row * OCW + HC + h * PVN * 3 + pp * 3 + 1] = ly;
        g_oc[(long)row * OCW + HC + h * PVN * 3 + pp * 3 + 2] = lz;
        g_oc[(long)row * OCW + HC + HPV3 + h * PVN + pp] =
            sqrtf(lx * lx + ly * ly + lz * lz + 1e-8f);
    }
}

// ---------------------------------------------------------------------------
// Finalize: warp per row, upd = oc @ wfold + bupd, quaternion update.
// ---------------------------------------------------------------------------
__global__ void finalize_kernel(const float* __restrict__ bupd,
                                float* __restrict__ out) {
    int gw = (blockIdx.x * blockDim.x + threadIdx.x) >> 5;
    int lane = threadIdx.x & 31;
    if (gw >= BB * PROW) return;
    int row = gw;
    int b = row / PROW, i = row % PROW;
    int ridx = b * TT + NPAD + i;

    float acc[6] = {0.f, 0.f, 0.f, 0.f, 0.f, 0.f};
    const float* ocr = g_oc + (long)row * OCW;
    for (int k = lane; k < OCW; k += 32) {
        float v = ocr[k];
#pragma unroll
        for (int j = 0; j < 6; j++) acc[j] += v * g_wfold[j * OCW + k];
    }
#pragma unroll
    for (int off = 16; off > 0; off >>= 1)
#pragma unroll
        for (int j = 0; j < 6; j++)
            acc[j] += __shfl_down_sync(0xffffffffu, acc[j], off);
    if (lane != 0) return;

    float u[6];
#pragma unroll
    for (int j = 0; j < 6; j++) u[j] = acc[j] + bupd[j];

    float bq = u[0], cq = u[1], dq = u[2];
    float ninv = rsqrtf(1.f + bq * bq + cq * cq + dq * dq);
    float w = ninv, x = bq * ninv, y = cq * ninv, z = dq * ninv;
    float Ru[9];
    Ru[0] = 1.f - 2.f * (y * y + z * z); Ru[1] = 2.f * (x * y - w * z); Ru[2] = 2.f * (x * z + w * y);
    Ru[3] = 2.f * (x * y + w * z); Ru[4] = 1.f - 2.f * (x * x + z * z); Ru[5] = 2.f * (y * z - w * x);
    Ru[6] = 2.f * (x * z - w * y); Ru[7] = 2.f * (y * z + w * x); Ru[8] = 1.f - 2.f * (x * x + y * y);

    float R[9];
#pragma unroll
    for (int r = 0; r < 9; r++) R[r] = g_r_all[ridx * 9 + r];

    float Rn[9];
#pragma unroll
    for (int r = 0; r < 3; r++)
#pragma unroll
        for (int c = 0; c < 3; c++) {
            float a = 0.f;
#pragma unroll
            for (int k = 0; k < 3; k++) a += R[r * 3 + k] * Ru[k * 3 + c];
            Rn[r * 3 + c] = a;
        }

    out[row * 3 + 0] = R[0] * u[3] + R[1] * u[4] + R[2] * u[5] + g_t_all[ridx * 3 + 0];
    out[row * 3 + 1] = R[3] * u[3] + R[4] * u[4] + R[5] * u[5] + g_t_all[ridx * 3 + 1];
    out[row * 3 + 2] = R[6] * u[3] + R[7] * u[4] + R[8] * u[5] + g_t_all[ridx * 3 + 2];
    float* rout = out + BB * PROW * 3;
#pragma unroll
    for (int r = 0; r < 9; r++) rout[row * 9 + r] = Rn[r];
}

// ---------------------------------------------------------------------------
extern "C" void kernel_launch(void* const* d_in, const int* in_sizes, int n_in,
                              void* d_out, int out_size) {
    const float* trans = (const float*)d_in[0];
    const float* rots  = (const float*)d_in[1];
    const float* s     = (const float*)d_in[2];
    const float* wq    = (const float*)d_in[3];
    const float* wk    = (const float*)d_in[4];
    const float* wv    = (const float*)d_in[5];
    const float* wqp   = (const float*)d_in[6];
    const float* wkp   = (const float*)d_in[7];
    const float* wvp   = (const float*)d_in[8];
    const float* gamma = (const float*)d_in[9];
    const float* wout  = (const float*)d_in[10];
    const float* wupd  = (const float*)d_in[11];
    const float* bupd  = (const float*)d_in[12];
    float* out = (float*)d_out;

    float *p_s_all, *p_k, *p_v, *p_kp, *p_vp, *p_q, *p_qp;
    cudaGetSymbolAddress((void**)&p_s_all, g_s_all);
    cudaGetSymbolAddress((void**)&p_k, g_k);
    cudaGetSymbolAddress((void**)&p_v, g_v);
    cudaGetSymbolAddress((void**)&p_kp, g_kp);
    cudaGetSymbolAddress((void**)&p_vp, g_vp);
    cudaGetSymbolAddress((void**)&p_q, g_q);
    cudaGetSymbolAddress((void**)&p_qp, g_qp);

    // 1. fused pooling prep
    prep_all_kernel<<<(S_TOT + TR_TOT + 255) / 256, 256>>>(s, trans, rots);

    // 2. all projection GEMMs in one launch
    TaskPack P;
    int Mfull = BB * TT;
    auto setTask = [&](int ti, const float* A, const float* B, float* C,
                       int M, int N, int K) {
        P.t[ti].A = A; P.t[ti].B = B; P.t[ti].C = C;
        P.t[ti].M = M; P.t[ti].N = N; P.t[ti].K = K;
        P.t[ti].gx = (N + GBN - 1) / GBN;
    };
    setTask(0, p_s_all, wk,  p_k,  Mfull, HC,   CSD);
    setTask(1, p_s_all, wv,  p_v,  Mfull, HC,   CSD);
    setTask(2, p_s_all, wkp, p_kp, Mfull, HPQ3, CSD);
    setTask(3, p_s_all, wvp, p_vp, Mfull, HPV3, CSD);
    setTask(4, p_s_all + (long)NPAD * CSD,        wq,  p_q,                      PROW, HC,   CSD);
    setTask(5, p_s_all + (long)(TT + NPAD) * CSD, wq,  p_q + (long)PROW * HC,    PROW, HC,   CSD);
    setTask(6, p_s_all + (long)NPAD * CSD,        wqp, p_qp,                     PROW, HPQ3, CSD);
    setTask(7, p_s_all + (long)(TT + NPAD) * CSD, wqp, p_qp + (long)PROW * HPQ3, PROW, HPQ3, CSD);
    P.ofs[0] = 0;
    for (int ti = 0; ti < NTASK; ti++) {
        int gy = (P.t[ti].M + GBM - 1) / GBM;
        P.ofs[ti + 1] = P.ofs[ti] + P.t[ti].gx * gy;
    }
    mgemm_kernel<<<P.ofs[NTASK], 256>>>(P);

    // 3. weight fold (warp per row)
    fold_w_kernel<<<(OCW * 32 + 255) / 256, 256>>>(wout, wupd);

    // 4. fused point transforms
    transform_all_kernel<<<(KV_TOT + Q_TOT + 255) / 256, 256>>>();

    // 5. split-KV attention
    attn_split_kernel<<<dim3(BB * HH, PROW / ATH, ATTS), ATH>>>(gamma);

    // 6. combine + build oc
    combine_oc_kernel<<<(BB * PROW * HH + 255) / 256, 256>>>();

    // 7. finalize (warp per row)
    finalize_kernel<<<(BB * PROW * 32 + 255) / 256, 256>>>(bupd, out);
}

// round 4
// speedup vs baseline: 1.1987x; 1.1987x over previous
#include <cuda_runtime.h>
#include <math.h>

// Problem constants
#define BB 2
#define NN 1024
#define CSD 384
#define HH 12
#define CC 16
#define PQN 4
#define PVN 8
#define NPAD 1026        // N + 2*PAD
#define PROW 512         // num_pool
#define TT 1538          // NPAD + PROW
#define HC 192           // H*C
#define HPQ3 144         // H*PQ*3
#define HPV3 288         // H*PV*3
#define OCW 576          // HC + HPV3 + H*PV
#define ATTS 4           // split-KV factor
#define ACHUNK ((TT + ATTS - 1) / ATTS)   // 385

#define C1 0.176776695f       // w_l * (1/sqrt(C))
#define WC_HALF 0.117851130f  // w_c/2

// Scratch (device globals)
__device__ float g_s_all[BB*TT*CSD];
__device__ float g_t_all[BB*TT*3];
__device__ float g_r_all[BB*TT*9];
__device__ float g_k  [BB*TT*HC];
__device__ float g_v  [BB*TT*HC];
__device__ float g_kp [BB*TT*HPQ3];
__device__ float g_vp [BB*TT*HPV3];
__device__ float g_sk [BB*TT*HH];
__device__ float g_q  [BB*PROW*HC];
__device__ float g_qp [BB*PROW*HPQ3];
__device__ float g_oc [BB*PROW*OCW];
__device__ float g_wfold[6*OCW];

#define NPART (BB*PROW*HH*ATTS)
__device__ float g_pm[NPART];
__device__ float g_pl[NPART];
__device__ float g_po[NPART*CC];
__device__ float g_pg[NPART*PVN*3];

__device__ __forceinline__ int clampsrc(int e) {
    int v = e - 1;
    return v < 0 ? 0 : (v > NN - 1 ? NN - 1 : v);
}

// ---------------------------------------------------------------------------
// Fused pooling prep: s_all then t/r
// ---------------------------------------------------------------------------
#define S_TOT (BB*TT*CSD)
#define TR_TOT (BB*TT*12)
__global__ void prep_all_kernel(const float* __restrict__ s,
                                const float* __restrict__ trans,
                                const float* __restrict__ rots) {
    int idx = blockIdx.x * blockDim.x + threadIdx.x;
    if (idx < S_TOT) {
        int c = idx % CSD;
        int bt = idx / CSD;
        int t = bt % TT;
        int b = bt / TT;
        float val;
        if (t < NPAD) {
            val = s[(b * NN + clampsrc(t)) * CSD + c];
        } else {
            int p = t - NPAD;
            val = (s[(b * NN + clampsrc(2 * p    )) * CSD + c]
                 + s[(b * NN + clampsrc(2 * p + 1)) * CSD + c]
                 + s[(b * NN + clampsrc(2 * p + 2)) * CSD + c]) * (1.f / 3.f);
        }
        g_s_all[idx] = val;
        return;
    }
    int k = idx - S_TOT;
    if (k >= TR_TOT) return;
    int d = k % 12;
    int bt = k / 12;
    int t = bt % TT;
    int b = bt / TT;
    if (d < 3) {
        float val;
        if (t < NPAD) {
            val = trans[(b * NN + clampsrc(t)) * 3 + d];
        } else {
            int p = t - NPAD;
            val = (trans[(b * NN + clampsrc(2 * p    )) * 3 + d]
                 + trans[(b * NN + clampsrc(2 * p + 1)) * 3 + d]
                 + trans[(b * NN + clampsrc(2 * p + 2)) * 3 + d]) * (1.f / 3.f);
        }
        g_t_all[(b * TT + t) * 3 + d] = val;
    } else {
        int r = d - 3;
        float val;
        if (t < NPAD) {
            val = rots[(b * NN + clampsrc(t)) * 9 + r];
        } else {
            int p = t - NPAD;
            val = (rots[(b * NN + clampsrc(2 * p    )) * 9 + r]
                 + rots[(b * NN + clampsrc(2 * p + 1)) * 9 + r]
                 + rots[(b * NN + clampsrc(2 * p + 2)) * 9 + r]) * (1.f / 3.f);
        }
        g_r_all[(b * TT + t) * 9 + r] = val;
    }
}

// ---------------------------------------------------------------------------
// Fused multi-task SGEMM: tile 64x64, BK=16, 256 threads, 4x4/thread.
// (round-2 proven config)
// ---------------------------------------------------------------------------
#define NTASK 8
struct GemmTask {
    const float* A;
    const float* B;
    float* C;
    int M, N, K, gx;
};
struct TaskPack {
    GemmTask t[NTASK];
    int ofs[NTASK + 1];
};

#define GBM 64
#define GBN 64
#define GBK 16
__global__ void mgemm_kernel(TaskPack P) {
    int bid = blockIdx.x;
    int ti = 0;
#pragma unroll
    for (int x = 0; x < NTASK - 1; x++)
        if (bid >= P.ofs[x + 1]) ti = x + 1;
    GemmTask tk = P.t[ti];
    int lb = bid - P.ofs[ti];
    int bx = lb % tk.gx, by = lb / tk.gx;

    __shared__ float As[GBK][GBM];
    __shared__ float Bs[GBK][GBN];
    int tid = threadIdx.x;
    int tx = tid % 16, ty = tid / 16;
    int row0 = by * GBM;
    int col0 = bx * GBN;
    const float* A = tk.A;
    const float* Bm = tk.B;
    int M = tk.M, Nn = tk.N, K = tk.K;

    float acc[4][4];
#pragma unroll
    for (int i = 0; i < 4; i++)
#pragma unroll
        for (int j = 0; j < 4; j++) acc[i][j] = 0.f;

    for (int k0 = 0; k0 < K; k0 += GBK) {
#pragma unroll
        for (int x = 0; x < (GBM * GBK) / 256; x++) {
            int li = tid + x * 256;
            int m = li / GBK, kk = li % GBK;
            int gm = row0 + m;
            As[kk][m] = (gm < M) ? A[(long)gm * K + k0 + kk] : 0.f;
        }
#pragma unroll
        for (int x = 0; x < (GBK * GBN) / 256; x++) {
            int li = tid + x * 256;
            int kk = li / GBN, n = li % GBN;
            int gn = col0 + n;
            Bs[kk][n] = (gn < Nn) ? Bm[(long)(k0 + kk) * Nn + gn] : 0.f;
        }
        __syncthreads();
#pragma unroll
        for (int kk = 0; kk < GBK; kk++) {
            float a[4], bvals[4];
#pragma unroll
            for (int i = 0; i < 4; i++) a[i] = As[kk][ty * 4 + i];
#pragma unroll
            for (int j = 0; j < 4; j++) bvals[j] = Bs[kk][tx * 4 + j];
#pragma unroll
            for (int i = 0; i < 4; i++)
#pragma unroll
                for (int j = 0; j < 4; j++) acc[i][j] += a[i] * bvals[j];
        }
        __syncthreads();
    }
#pragma unroll
    for (int i = 0; i < 4; i++) {
        int gm = row0 + ty * 4 + i;
        if (gm >= M) continue;
#pragma unroll
        for (int j = 0; j < 4; j++) {
            int gn = col0 + tx * 4 + j;
            if (gn < Nn) tk.C[(long)gm * Nn + gn] = acc[i][j];
        }
    }
}

// ---------------------------------------------------------------------------
// Weight fold: warp per OCW-row.
// ---------------------------------------------------------------------------
__global__ void fold_w_kernel(const float* __restrict__ wout,
                              const float* __restrict__ wupd) {
    int gw = (blockIdx.x * blockDim.x + threadIdx.x) >> 5;
    int lane = threadIdx.x & 31;
    if (gw >= OCW) return;
    const float* wr = wout + (long)gw * CSD;
    float acc[6] = {0, 0, 0, 0, 0, 0};
    for (int m = lane; m < CSD; m += 32) {
        float w = wr[m];
#pragma unroll
        for (int j = 0; j < 6; j++) acc[j] += w * __ldg(&wupd[m * 6 + j]);
    }
#pragma unroll
    for (int off = 16; off > 0; off >>= 1)
#pragma unroll
        for (int j = 0; j < 6; j++)
            acc[j] += __shfl_down_sync(0xffffffffu, acc[j], off);
    if (lane == 0) {
#pragma unroll
        for (int j = 0; j < 6; j++) g_wfold[j * OCW + gw] = acc[j];
    }
}

// ---------------------------------------------------------------------------
// Fused point transforms: kv (all rows) + q (pooled rows).
// ---------------------------------------------------------------------------
#define KV_TOT (BB*TT*HH)
#define Q_TOT (BB*PROW*HH)
__global__ void transform_all_kernel() {
    int idx = blockIdx.x * blockDim.x + threadIdx.x;
    if (idx < KV_TOT) {
        int h = idx % HH;
        int rt = idx / HH;
        float R[9], tr[3];
#pragma unroll
        for (int r = 0; r < 9; r++) R[r] = g_r_all[rt * 9 + r];
#pragma unroll
        for (int r = 0; r < 3; r++) tr[r] = g_t_all[rt * 3 + r];

        float sk = 0.f;
        int kb = rt * HPQ3 + h * PQN * 3;
#pragma unroll
        for (int p = 0; p < PQN; p++) {
            float lx = g_kp[kb + p * 3 + 0];
            float ly = g_kp[kb + p * 3 + 1];
            float lz = g_kp[kb + p * 3 + 2];
            float gx = R[0] * lx + R[1] * ly + R[2] * lz + tr[0];
            float gy = R[3] * lx + R[4] * ly + R[5] * lz + tr[1];
            float gz = R[6] * lx + R[7] * ly + R[8] * lz + tr[2];
            g_kp[kb + p * 3 + 0] = gx;
            g_kp[kb + p * 3 + 1] = gy;
            g_kp[kb + p * 3 + 2] = gz;
            sk += gx * gx + gy * gy + gz * gz;
        }
        g_sk[rt * HH + h] = sk;

        int vb = rt * HPV3 + h * PVN * 3;
#pragma unroll
        for (int p = 0; p < PVN; p++) {
            float lx = g_vp[vb + p * 3 + 0];
            float ly = g_vp[vb + p * 3 + 1];
            float lz = g_vp[vb + p * 3 + 2];
            float gx = R[0] * lx + R[1] * ly + R[2] * lz + tr[0];
            float gy = R[3] * lx + R[4] * ly + R[5] * lz + tr[1];
            float gz = R[6] * lx + R[7] * ly + R[8] * lz + tr[2];
            g_vp[vb + p * 3 + 0] = gx;
            g_vp[vb + p * 3 + 1] = gy;
            g_vp[vb + p * 3 + 2] = gz;
        }
        return;
    }
    int k = idx - KV_TOT;
    if (k >= Q_TOT) return;
    int h = k % HH;
    int row = k / HH;
    int b = row / PROW, i = row % PROW;
    int ridx = b * TT + NPAD + i;
    float R[9], tr[3];
#pragma unroll
    for (int r = 0; r < 9; r++) R[r] = g_r_all[ridx * 9 + r];
#pragma unroll
    for (int r = 0; r < 3; r++) tr[r] = g_t_all[ridx * 3 + r];
    int qb = row * HPQ3 + h * PQN * 3;
#pragma unroll
    for (int p = 0; p < PQN; p++) {
        float lx = g_qp[qb + p * 3 + 0];
        float ly = g_qp[qb + p * 3 + 1];
        float lz = g_qp[qb + p * 3 + 2];
        float gx = R[0] * lx + R[1] * ly + R[2] * lz + tr[0];
        float gy = R[3] * lx + R[4] * ly + R[5] * lz + tr[1];
        float gz = R[6] * lx + R[7] * ly + R[8] * lz + tr[2];
        g_qp[qb + p * 3 + 0] = gx;
        g_qp[qb + p * 3 + 1] = gy;
        g_qp[qb + p * 3 + 2] = gz;
    }
}

// ---------------------------------------------------------------------------
// Split-KV attention (round-2 proven config): grid (B*H, PROW/64, ATTS=4),
// 64 threads/block, TJ=32 tiles, float4 smem.
// ---------------------------------------------------------------------------
#define TJ 32
#define ATH 64
__global__ void attn_split_kernel(const float* __restrict__ gamma) {
    int bh = blockIdx.x;
    int b = bh / HH, h = bh % HH;
    int i = blockIdx.y * ATH + threadIdx.x;
    int sp = blockIdx.z;
    int tid = threadIdx.x;

    int j_begin = sp * ACHUNK;
    int j_end = j_begin + ACHUNK;
    if (j_end > TT) j_end = TT;

    __shared__ __align__(16) float k_s [TJ][CC];
    __shared__ __align__(16) float v_s [TJ][CC];
    __shared__ __align__(16) float kg_s[TJ][PQN * 3];
    __shared__ __align__(16) float vg_s[TJ][PVN * 3];
    __shared__ float sk_s[TJ];

    int qrow = b * PROW + i;
    float q[CC], qg[PQN * 3];
    {
        const float4* q4 = reinterpret_cast<const float4*>(g_q + (long)qrow * HC + h * CC);
#pragma unroll
        for (int c = 0; c < 4; c++) {
            float4 v = q4[c];
            q[c*4+0] = v.x; q[c*4+1] = v.y; q[c*4+2] = v.z; q[c*4+3] = v.w;
        }
        const float4* g4 = reinterpret_cast<const float4*>(g_qp + (long)qrow * HPQ3 + h * PQN * 3);
#pragma unroll
        for (int c = 0; c < 3; c++) {
            float4 v = g4[c];
            qg[c*4+0] = v.x; qg[c*4+1] = v.y; qg[c*4+2] = v.z; qg[c*4+3] = v.w;
        }
    }
    float sq = 0.f;
#pragma unroll
    for (int x = 0; x < PQN * 3; x++) sq += qg[x] * qg[x];

    float gm = gamma[h];
    float gcoef = logf(1.f + __expf(gm)) * WC_HALF;

    float mrun = -1e30f, lrun = 0.f;
    float ao[CC], ag[PVN * 3];
#pragma unroll
    for (int c = 0; c < CC; c++) ao[c] = 0.f;
#pragma unroll
    for (int x = 0; x < PVN * 3; x++) ag[x] = 0.f;

    for (int j0 = j_begin; j0 < j_end; j0 += TJ) {
        __syncthreads();
        for (int x = tid; x < TJ * 4; x += ATH) {
            int j = x >> 2, c4 = x & 3;
            int jj = j0 + j;
            float4 v = (jj < TT)
                ? reinterpret_cast<const float4*>(g_k + ((long)(b * TT + jj) * HC + h * CC))[c4]
                : make_float4(0.f, 0.f, 0.f, 0.f);
            reinterpret_cast<float4*>(&k_s[j][0])[c4] = v;
        }
        for (int x = tid; x < TJ * 4; x += ATH) {
            int j = x >> 2, c4 = x & 3;
            int jj = j0 + j;
            float4 v = (jj < TT)
                ? reinterpret_cast<const float4*>(g_v + ((long)(b * TT + jj) * HC + h * CC))[c4]
                : make_float4(0.f, 0.f, 0.f, 0.f);
            reinterpret_cast<float4*>(&v_s[j][0])[c4] = v;
        }
        for (int x = tid; x < TJ * 3; x += ATH) {
            int j = x / 3, c4 = x % 3;
            int jj = j0 + j;
            float4 v = (jj < TT)
                ? reinterpret_cast<const float4*>(g_kp + ((long)(b * TT + jj) * HPQ3 + h * PQN * 3))[c4]
                : make_float4(0.f, 0.f, 0.f, 0.f);
            reinterpret_cast<float4*>(&kg_s[j][0])[c4] = v;
        }
        for (int x = tid; x < TJ * 6; x += ATH) {
            int j = x / 6, c4 = x % 6;
            int jj = j0 + j;
            float4 v = (jj < TT)
                ? reinterpret_cast<const float4*>(g_vp + ((long)(b * TT + jj) * HPV3 + h * PVN * 3))[c4]
                : make_float4(0.f, 0.f, 0.f, 0.f);
            reinterpret_cast<float4*>(&vg_s[j][0])[c4] = v;
        }
        for (int x = tid; x < TJ; x += ATH) {
            int jj = j0 + x;
            sk_s[x] = (jj < TT) ? g_sk[(long)(b * TT + jj) * HH + h] : 0.f;
        }
        __syncthreads();

        int nv = j_end - j0;
        if (nv > TJ) nv = TJ;

        float logit[TJ];
        float tmax = -1e30f;
#pragma unroll
        for (int jj = 0; jj < TJ; jj++) {
            float qk = 0.f;
            const float4* k4 = reinterpret_cast<const float4*>(&k_s[jj][0]);
#pragma unroll
            for (int c = 0; c < 4; c++) {
                float4 kv = k4[c];
                qk += q[c*4+0] * kv.x + q[c*4+1] * kv.y + q[c*4+2] * kv.z + q[c*4+3] * kv.w;
            }
            float dt = 0.f;
            const float4* g4 = reinterpret_cast<const float4*>(&kg_s[jj][0]);
#pragma unroll
            for (int c = 0; c < 3; c++) {
                float4 kv = g4[c];
                dt += qg[c*4+0] * kv.x + qg[c*4+1] * kv.y + qg[c*4+2] * kv.z + qg[c*4+3] * kv.w;
            }
            float d2 = sq + sk_s[jj] - 2.f * dt;
            float lg = C1 * qk - gcoef * d2;
            logit[jj] = (jj < nv) ? lg : -1e30f;
            tmax = fmaxf(tmax, logit[jj]);
        }
        float mn = fmaxf(mrun, tmax);
        float corr = __expf(mrun - mn);
        lrun *= corr;
#pragma unroll
        for (int c = 0; c < CC; c++) ao[c] *= corr;
#pragma unroll
        for (int x = 0; x < PVN * 3; x++) ag[x] *= corr;
#pragma unroll
        for (int jj = 0; jj < TJ; jj++) {
            float e = __expf(logit[jj] - mn);
            lrun += e;
            const float4* v4 = reinterpret_cast<const float4*>(&v_s[jj][0]);
#pragma unroll
            for (int c = 0; c < 4; c++) {
                float4 vv = v4[c];
                ao[c*4+0] += e * vv.x; ao[c*4+1] += e * vv.y;
                ao[c*4+2] += e * vv.z; ao[c*4+3] += e * vv.w;
            }
            const float4* g4 = reinterpret_cast<const float4*>(&vg_s[jj][0]);
#pragma unroll
            for (int c = 0; c < 6; c++) {
                float4 vv = g4[c];
                ag[c*4+0] += e * vv.x; ag[c*4+1] += e * vv.y;
                ag[c*4+2] += e * vv.z; ag[c*4+3] += e * vv.w;
            }
        }
        mrun = mn;
    }

    int p = (qrow * HH + h) * ATTS + sp;
    g_pm[p] = mrun;
    g_pl[p] = lrun;
#pragma unroll
    for (int c = 0; c < CC; c++) g_po[(long)p * CC + c] = ao[c];
#pragma unroll
    for (int x = 0; x < PVN * 3; x++) g_pg[(long)p * (PVN * 3) + x] = ag[x];
}

// ---------------------------------------------------------------------------
// Combine split partials + build oc rows. One thread per (b,i,h).
// ---------------------------------------------------------------------------
__global__ void combine_oc_kernel() {
    int idx = blockIdx.x * blockDim.x + threadIdx.x;
    if (idx >= BB * PROW * HH) return;
    int h = idx % HH;
    int row = idx / HH;
    int b = row / PROW, i = row % PROW;
    int p0 = idx * ATTS;

    float m = -1e30f;
#pragma unroll
    for (int s = 0; s < ATTS; s++) m = fmaxf(m, g_pm[p0 + s]);
    float L = 0.f;
    float o[CC], g[PVN * 3];
#pragma unroll
    for (int c = 0; c < CC; c++) o[c] = 0.f;
#pragma unroll
    for (int x = 0; x < PVN * 3; x++) g[x] = 0.f;
#pragma unroll
    for (int s = 0; s < ATTS; s++) {
        float w = __expf(g_pm[p0 + s] - m);
        L += g_pl[p0 + s] * w;
        const float* po = g_po + (long)(p0 + s) * CC;
        const float* pg = g_pg + (long)(p0 + s) * (PVN * 3);
#pragma unroll
        for (int c = 0; c < CC; c++) o[c] += w * po[c];
#pragma unroll
        for (int x = 0; x < PVN * 3; x++) g[x] += w * pg[x];
    }
    float inv = 1.f / L;
#pragma unroll
    for (int c = 0; c < CC; c++) o[c] *= inv;
#pragma unroll
    for (int x = 0; x < PVN * 3; x++) g[x] *= inv;

    int ridx = b * TT + NPAD + i;
    float R[9], tr[3];
#pragma unroll
    for (int r = 0; r < 9; r++) R[r] = g_r_all[ridx * 9 + r];
#pragma unroll
    for (int r = 0; r < 3; r++) tr[r] = g_t_all[ridx * 3 + r];

#pragma unroll
    for (int c = 0; c < CC; c++)
        g_oc[(long)row * OCW + h * CC + c] = o[c];

#pragma unroll
    for (int pp = 0; pp < PVN; pp++) {
        float gx = g[pp * 3 + 0] - tr[0];
        float gy = g[pp * 3 + 1] - tr[1];
        float gz = g[pp * 3 + 2] - tr[2];
        float lx = R[0] * gx + R[3] * gy + R[6] * gz;
        float ly = R[1] * gx + R[4] * gy + R[7] * gz;
        float lz = R[2] * gx + R[5] * gy + R[8] * gz;
        g_oc[(long)row * OCW + HC + h * PVN * 3 + pp * 3 + 0] = lx;
        g_oc[(long)row * OCW + HC + h * PVN * 3 + pp * 3 + 1] = ly;
        g_oc[(long)row * OCW + HC + h * PVN * 3 + pp * 3 + 2] = lz;
        g_oc[(long)row * OCW + HC + HPV3 + h * PVN + pp] =
            sqrtf(lx * lx + ly * ly + lz * lz + 1e-8f);
    }
}

// ---------------------------------------------------------------------------
// Finalize: warp per row.
// ---------------------------------------------------------------------------
__global__ void finalize_kernel(const float* __restrict__ bupd,
                                float* __restrict__ out) {
    int gw = (blockIdx.x * blockDim.x + threadIdx.x) >> 5;
    int lane = threadIdx.x & 31;
    if (gw >= BB * PROW) return;
    int row = gw;
    int b = row / PROW, i = row % PROW;
    int ridx = b * TT + NPAD + i;

    float acc[6] = {0.f, 0.f, 0.f, 0.f, 0.f, 0.f};
    const float* ocr = g_oc + (long)row * OCW;
    for (int k = lane; k < OCW; k += 32) {
        float v = ocr[k];
#pragma unroll
        for (int j = 0; j < 6; j++) acc[j] += v * g_wfold[j * OCW + k];
    }
#pragma unroll
    for (int off = 16; off > 0; off >>= 1)
#pragma unroll
        for (int j = 0; j < 6; j++)
            acc[j] += __shfl_down_sync(0xffffffffu, acc[j], off);
    if (lane != 0) return;

    float u[6];
#pragma unroll
    for (int j = 0; j < 6; j++) u[j] = acc[j] + bupd[j];

    float bq = u[0], cq = u[1], dq = u[2];
    float ninv = rsqrtf(1.f + bq * bq + cq * cq + dq * dq);
    float w = ninv, x = bq * ninv, y = cq * ninv, z = dq * ninv;
    float Ru[9];
    Ru[0] = 1.f - 2.f * (y * y + z * z); Ru[1] = 2.f * (x * y - w * z); Ru[2] = 2.f * (x * z + w * y);
    Ru[3] = 2.f * (x * y + w * z); Ru[4] = 1.f - 2.f * (x * x + z * z); Ru[5] = 2.f * (y * z - w * x);
    Ru[6] = 2.f * (x * z - w * y); Ru[7] = 2.f * (y * z + w * x); Ru[8] = 1.f - 2.f * (x * x + y * y);

    float R[9];
#pragma unroll
    for (int r = 0; r < 9; r++) R[r] = g_r_all[ridx * 9 + r];

    float Rn[9];
#pragma unroll
    for (int r = 0; r < 3; r++)
#pragma unroll
        for (int c = 0; c < 3; c++) {
            float a = 0.f;
#pragma unroll
            for (int k = 0; k < 3; k++) a += R[r * 3 + k] * Ru[k * 3 + c];
            Rn[r * 3 + c] = a;
        }

    out[row * 3 + 0] = R[0] * u[3] + R[1] * u[4] + R[2] * u[5] + g_t_all[ridx * 3 + 0];
    out[row * 3 + 1] = R[3] * u[3] + R[4] * u[4] + R[5] * u[5] + g_t_all[ridx * 3 + 1];
    out[row * 3 + 2] = R[6] * u[3] + R[7] * u[4] + R[8] * u[5] + g_t_all[ridx * 3 + 2];
    float* rout = out + BB * PROW * 3;
#pragma unroll
    for (int r = 0; r < 9; r++) rout[row * 9 + r] = Rn[r];
}

// ---------------------------------------------------------------------------
extern "C" void kernel_launch(void* const* d_in, const int* in_sizes, int n_in,
                              void* d_out, int out_size) {
    const float* trans = (const float*)d_in[0];
    const float* rots  = (const float*)d_in[1];
    const float* s     = (const float*)d_in[2];
    const float* wq    = (const float*)d_in[3];
    const float* wk    = (const float*)d_in[4];
    const float* wv    = (const float*)d_in[5];
    const float* wqp   = (const float*)d_in[6];
    const float* wkp   = (const float*)d_in[7];
    const float* wvp   = (const float*)d_in[8];
    const float* gamma = (const float*)d_in[9];
    const float* wout  = (const float*)d_in[10];
    const float* wupd  = (const float*)d_in[11];
    const float* bupd  = (const float*)d_in[12];
    float* out = (float*)d_out;

    float *p_s_all, *p_k, *p_v, *p_kp, *p_vp, *p_q, *p_qp;
    cudaGetSymbolAddress((void**)&p_s_all, g_s_all);
    cudaGetSymbolAddress((void**)&p_k, g_k);
    cudaGetSymbolAddress((void**)&p_v, g_v);
    cudaGetSymbolAddress((void**)&p_kp, g_kp);
    cudaGetSymbolAddress((void**)&p_vp, g_vp);
    cudaGetSymbolAddress((void**)&p_q, g_q);
    cudaGetSymbolAddress((void**)&p_qp, g_qp);

    // 1. fused pooling prep
    prep_all_kernel<<<(S_TOT + TR_TOT + 255) / 256, 256>>>(s, trans, rots);

    // 2. all projection GEMMs in one launch (64x64 tiles)
    TaskPack P;
    int Mfull = BB * TT;
    auto setTask = [&](int ti, const float* A, const float* B, float* C,
                       int M, int N, int K) {
        P.t[ti].A = A; P.t[ti].B = B; P.t[ti].C = C;
        P.t[ti].M = M; P.t[ti].N = N; P.t[ti].K = K;
        P.t[ti].gx = (N + GBN - 1) / GBN;
    };
    setTask(0, p_s_all, wk,  p_k,  Mfull, HC,   CSD);
    setTask(1, p_s_all, wv,  p_v,  Mfull, HC,   CSD);
    setTask(2, p_s_all, wkp, p_kp, Mfull, HPQ3, CSD);
    setTask(3, p_s_all, wvp, p_vp, Mfull, HPV3, CSD);
    setTask(4, p_s_all + (long)NPAD * CSD,        wq,  p_q,                      PROW, HC,   CSD);
    setTask(5, p_s_all + (long)(TT + NPAD) * CSD, wq,  p_q + (long)PROW * HC,    PROW, HC,   CSD);
    setTask(6, p_s_all + (long)NPAD * CSD,        wqp, p_qp,                     PROW, HPQ3, CSD);
    setTask(7, p_s_all + (long)(TT + NPAD) * CSD, wqp, p_qp + (long)PROW * HPQ3, PROW, HPQ3, CSD);
    P.ofs[0] = 0;
    for (int ti = 0; ti < NTASK; ti++) {
        int gy = (P.t[ti].M + GBM - 1) / GBM;
        P.ofs[ti + 1] = P.ofs[ti] + P.t[ti].gx * gy;
    }
    mgemm_kernel<<<P.ofs[NTASK], 256>>>(P);

    // 3. weight fold (warp per row)
    fold_w_kernel<<<(OCW * 32 + 255) / 256, 256>>>(wout, wupd);

    // 4. fused point transforms
    transform_all_kernel<<<(KV_TOT + Q_TOT + 255) / 256, 256>>>();

    // 5. split-KV attention (ATTS=4, 64 threads)
    attn_split_kernel<<<dim3(BB * HH, PROW / ATH, ATTS), ATH>>>(gamma);

    // 6. combine + build oc
    combine_oc_kernel<<<(BB * PROW * HH + 255) / 256, 256>>>();

    // 7. finalize (warp per row)
    finalize_kernel<<<(BB * PROW * 32 + 255) / 256, 256>>>(bupd, out);
}

// round 5
// speedup vs baseline: 1.3750x; 1.1471x over previous
#include <cuda_runtime.h>
#include <math.h>

// Problem constants
#define BB 2
#define NN 1024
#define CSD 384
#define HH 12
#define CC 16
#define PQN 4
#define PVN 8
#define NPAD 1026        // N + 2*PAD
#define PROW 512         // num_pool
#define TT 1538          // NPAD + PROW
#define HC 192           // H*C
#define HPQ3 144         // H*PQ*3
#define HPV3 288         // H*PV*3
#define OCW 576          // HC + HPV3 + H*PV
#define ATTS 4           // split-KV factor
#define ACHUNK ((TT + ATTS - 1) / ATTS)   // 385

#define C1 0.176776695f       // w_l * (1/sqrt(C))
#define WC_HALF 0.117851130f  // w_c/2

// Scratch (device globals)
__device__ float g_s_pool[BB*PROW*CSD];   // pooled s rows only
__device__ float g_t_all[BB*TT*3];
__device__ float g_r_all[BB*TT*9];
// raw-row projections (M = BB*NN)
__device__ float g_k0 [BB*NN*HC];
__device__ float g_v0 [BB*NN*HC];
__device__ float g_kp0[BB*NN*HPQ3];
__device__ float g_vp0[BB*NN*HPV3];
// expanded (TT rows) tensors consumed by attention
__device__ float g_k  [BB*TT*HC];
__device__ float g_v  [BB*TT*HC];
__device__ float g_kp [BB*TT*HPQ3];
__device__ float g_vp [BB*TT*HPV3];
__device__ float g_sk [BB*TT*HH];
__device__ float g_q  [BB*PROW*HC];
__device__ float g_qp [BB*PROW*HPQ3];
__device__ float g_oc [BB*PROW*OCW];
__device__ float g_wfold[6*OCW];

#define NPART (BB*PROW*HH*ATTS)
__device__ float g_pm[NPART];
__device__ float g_pl[NPART];
__device__ float g_po[NPART*CC];
__device__ float g_pg[NPART*PVN*3];

__device__ __forceinline__ int clampsrc(int e) {
    int v = e - 1;
    return v < 0 ? 0 : (v > NN - 1 ? NN - 1 : v);
}

// ---------------------------------------------------------------------------
// Prep: pooled s rows (for q/qp GEMM) + t_all / r_all (full TT rows)
// ---------------------------------------------------------------------------
#define SP_TOT (BB*PROW*CSD)
#define TR_TOT (BB*TT*12)
__global__ void prep_all_kernel(const float* __restrict__ s,
                                const float* __restrict__ trans,
                                const float* __restrict__ rots) {
    int idx = blockIdx.x * blockDim.x + threadIdx.x;
    if (idx < SP_TOT) {
        int c = idx % CSD;
        int bp = idx / CSD;
        int p = bp % PROW;
        int b = bp / PROW;
        g_s_pool[idx] = (s[(b * NN + clampsrc(2 * p    )) * CSD + c]
                       + s[(b * NN + clampsrc(2 * p + 1)) * CSD + c]
                       + s[(b * NN + clampsrc(2 * p + 2)) * CSD + c]) * (1.f / 3.f);
        return;
    }
    int k = idx - SP_TOT;
    if (k >= TR_TOT) return;
    int d = k % 12;
    int bt = k / 12;
    int t = bt % TT;
    int b = bt / TT;
    if (d < 3) {
        float val;
        if (t < NPAD) {
            val = trans[(b * NN + clampsrc(t)) * 3 + d];
        } else {
            int p = t - NPAD;
            val = (trans[(b * NN + clampsrc(2 * p    )) * 3 + d]
                 + trans[(b * NN + clampsrc(2 * p + 1)) * 3 + d]
                 + trans[(b * NN + clampsrc(2 * p + 2)) * 3 + d]) * (1.f / 3.f);
        }
        g_t_all[(b * TT + t) * 3 + d] = val;
    } else {
        int r = d - 3;
        float val;
        if (t < NPAD) {
            val = rots[(b * NN + clampsrc(t)) * 9 + r];
        } else {
            int p = t - NPAD;
            val = (rots[(b * NN + clampsrc(2 * p    )) * 9 + r]
                 + rots[(b * NN + clampsrc(2 * p + 1)) * 9 + r]
                 + rots[(b * NN + clampsrc(2 * p + 2)) * 9 + r]) * (1.f / 3.f);
        }
        g_r_all[(b * TT + t) * 9 + r] = val;
    }
}

// ---------------------------------------------------------------------------
// Fused multi-task SGEMM: tile 64x64, BK=16, 256 threads, 4x4/thread.
// ---------------------------------------------------------------------------
#define NTASK 6
struct GemmTask {
    const float* A;
    const float* B;
    float* C;
    int M, N, K, gx;
};
struct TaskPack {
    GemmTask t[NTASK];
    int ofs[NTASK + 1];
};

#define GBM 64
#define GBN 64
#define GBK 16
__global__ void mgemm_kernel(TaskPack P) {
    int bid = blockIdx.x;
    int ti = 0;
#pragma unroll
    for (int x = 0; x < NTASK - 1; x++)
        if (bid >= P.ofs[x + 1]) ti = x + 1;
    GemmTask tk = P.t[ti];
    int lb = bid - P.ofs[ti];
    int bx = lb % tk.gx, by = lb / tk.gx;

    __shared__ float As[GBK][GBM];
    __shared__ float Bs[GBK][GBN];
    int tid = threadIdx.x;
    int tx = tid % 16, ty = tid / 16;
    int row0 = by * GBM;
    int col0 = bx * GBN;
    const float* A = tk.A;
    const float* Bm = tk.B;
    int M = tk.M, Nn = tk.N, K = tk.K;

    float acc[4][4];
#pragma unroll
    for (int i = 0; i < 4; i++)
#pragma unroll
        for (int j = 0; j < 4; j++) acc[i][j] = 0.f;

    for (int k0 = 0; k0 < K; k0 += GBK) {
#pragma unroll
        for (int x = 0; x < (GBM * GBK) / 256; x++) {
            int li = tid + x * 256;
            int m = li / GBK, kk = li % GBK;
            int gm = row0 + m;
            As[kk][m] = (gm < M) ? A[(long)gm * K + k0 + kk] : 0.f;
        }
#pragma unroll
        for (int x = 0; x < (GBK * GBN) / 256; x++) {
            int li = tid + x * 256;
            int kk = li / GBN, n = li % GBN;
            int gn = col0 + n;
            Bs[kk][n] = (gn < Nn) ? Bm[(long)(k0 + kk) * Nn + gn] : 0.f;
        }
        __syncthreads();
#pragma unroll
        for (int kk = 0; kk < GBK; kk++) {
            float a[4], bvals[4];
#pragma unroll
            for (int i = 0; i < 4; i++) a[i] = As[kk][ty * 4 + i];
#pragma unroll
            for (int j = 0; j < 4; j++) bvals[j] = Bs[kk][tx * 4 + j];
#pragma unroll
            for (int i = 0; i < 4; i++)
#pragma unroll
                for (int j = 0; j < 4; j++) acc[i][j] += a[i] * bvals[j];
        }
        __syncthreads();
    }
#pragma unroll
    for (int i = 0; i < 4; i++) {
        int gm = row0 + ty * 4 + i;
        if (gm >= M) continue;
#pragma unroll
        for (int j = 0; j < 4; j++) {
            int gn = col0 + tx * 4 + j;
            if (gn < Nn) tk.C[(long)gm * Nn + gn] = acc[i][j];
        }
    }
}

// ---------------------------------------------------------------------------
// Weight fold: warp per OCW-row.
// ---------------------------------------------------------------------------
__global__ void fold_w_kernel(const float* __restrict__ wout,
                              const float* __restrict__ wupd) {
    int gw = (blockIdx.x * blockDim.x + threadIdx.x) >> 5;
    int lane = threadIdx.x & 31;
    if (gw >= OCW) return;
    const float* wr = wout + (long)gw * CSD;
    float acc[6] = {0, 0, 0, 0, 0, 0};
    for (int m = lane; m < CSD; m += 32) {
        float w = wr[m];
#pragma unroll
        for (int j = 0; j < 6; j++) acc[j] += w * __ldg(&wupd[m * 6 + j]);
    }
#pragma unroll
    for (int off = 16; off > 0; off >>= 1)
#pragma unroll
        for (int j = 0; j < 6; j++)
            acc[j] += __shfl_down_sync(0xffffffffu, acc[j], off);
    if (lane == 0) {
#pragma unroll
        for (int j = 0; j < 6; j++) g_wfold[j * OCW + gw] = acc[j];
    }
}

// ---------------------------------------------------------------------------
// Expand raw-row projections to TT rows (clamp / 3-avg) + transform points
// to global frame + sk.  Also transforms q points (pooled rows).
// One thread per (b,t,h) / (b,i,h).
// ---------------------------------------------------------------------------
#define KV_TOT (BB*TT*HH)
#define Q_TOT (BB*PROW*HH)
__device__ __forceinline__ float4 avg3f4(float4 a, float4 b, float4 c) {
    return make_float4((a.x + b.x + c.x) * (1.f / 3.f),
                       (a.y + b.y + c.y) * (1.f / 3.f),
                       (a.z + b.z + c.z) * (1.f / 3.f),
                       (a.w + b.w + c.w) * (1.f / 3.f));
}
__global__ void expand_transform_kernel() {
    int idx = blockIdx.x * blockDim.x + threadIdx.x;
    if (idx < KV_TOT) {
        int h = idx % HH;
        int rt = idx / HH;         // b*TT + t
        int t = rt % TT;
        int b = rt / TT;

        int r0, r1 = 0, r2 = 0;
        bool pool;
        if (t < NPAD) {
            r0 = clampsrc(t);
            pool = false;
        } else {
            int p = t - NPAD;
            r0 = clampsrc(2 * p);
            r1 = clampsrc(2 * p + 1);
            r2 = clampsrc(2 * p + 2);
            pool = true;
        }

        // --- k, v: copy or average (no rotation) ---
        {
            const float4* a = reinterpret_cast<const float4*>(g_k0 + ((long)(b * NN + r0) * HC + h * CC));
            const float4* bb = reinterpret_cast<const float4*>(g_k0 + ((long)(b * NN + r1) * HC + h * CC));
            const float4* cc = reinterpret_cast<const float4*>(g_k0 + ((long)(b * NN + r2) * HC + h * CC));
            float4* dst = reinterpret_cast<float4*>(g_k + ((long)rt * HC + h * CC));
#pragma unroll
            for (int c = 0; c < 4; c++)
                dst[c] = pool ? avg3f4(a[c], bb[c], cc[c]) : a[c];
        }
        {
            const float4* a = reinterpret_cast<const float4*>(g_v0 + ((long)(b * NN + r0) * HC + h * CC));
            const float4* bb = reinterpret_cast<const float4*>(g_v0 + ((long)(b * NN + r1) * HC + h * CC));
            const float4* cc = reinterpret_cast<const float4*>(g_v0 + ((long)(b * NN + r2) * HC + h * CC));
            float4* dst = reinterpret_cast<float4*>(g_v + ((long)rt * HC + h * CC));
#pragma unroll
            for (int c = 0; c < 4; c++)
                dst[c] = pool ? avg3f4(a[c], bb[c], cc[c]) : a[c];
        }

        float R[9], tr[3];
#pragma unroll
        for (int r = 0; r < 9; r++) R[r] = g_r_all[rt * 9 + r];
#pragma unroll
        for (int r = 0; r < 3; r++) tr[r] = g_t_all[rt * 3 + r];

        // --- kp: expand local points, rotate, sk ---
        {
            float lp[PQN * 3];
            const float4* a = reinterpret_cast<const float4*>(g_kp0 + ((long)(b * NN + r0) * HPQ3 + h * PQN * 3));
            const float4* bb = reinterpret_cast<const float4*>(g_kp0 + ((long)(b * NN + r1) * HPQ3 + h * PQN * 3));
            const float4* cc = reinterpret_cast<const float4*>(g_kp0 + ((long)(b * NN + r2) * HPQ3 + h * PQN * 3));
#pragma unroll
            for (int c = 0; c < 3; c++) {
                float4 v = pool ? avg3f4(a[c], bb[c], cc[c]) : a[c];
                lp[c*4+0] = v.x; lp[c*4+1] = v.y; lp[c*4+2] = v.z; lp[c*4+3] = v.w;
            }
            float sk = 0.f;
            float gp[PQN * 3];
#pragma unroll
            for (int p = 0; p < PQN; p++) {
                float lx = lp[p*3+0], ly = lp[p*3+1], lz = lp[p*3+2];
                float gx = R[0]*lx + R[1]*ly + R[2]*lz + tr[0];
                float gy = R[3]*lx + R[4]*ly + R[5]*lz + tr[1];
                float gz = R[6]*lx + R[7]*ly + R[8]*lz + tr[2];
                gp[p*3+0] = gx; gp[p*3+1] = gy; gp[p*3+2] = gz;
                sk += gx*gx + gy*gy + gz*gz;
            }
            g_sk[rt * HH + h] = sk;
            float4* dst = reinterpret_cast<float4*>(g_kp + ((long)rt * HPQ3 + h * PQN * 3));
#pragma unroll
            for (int c = 0; c < 3; c++)
                dst[c] = make_float4(gp[c*4+0], gp[c*4+1], gp[c*4+2], gp[c*4+3]);
        }
        // --- vp ---
        {
            float lp[PVN * 3];
            const float4* a = reinterpret_cast<const float4*>(g_vp0 + ((long)(b * NN + r0) * HPV3 + h * PVN * 3));
            const float4* bb = reinterpret_cast<const float4*>(g_vp0 + ((long)(b * NN + r1) * HPV3 + h * PVN * 3));
            const float4* cc = reinterpret_cast<const float4*>(g_vp0 + ((long)(b * NN + r2) * HPV3 + h * PVN * 3));
#pragma unroll
            for (int c = 0; c < 6; c++) {
                float4 v = pool ? avg3f4(a[c], bb[c], cc[c]) : a[c];
                lp[c*4+0] = v.x; lp[c*4+1] = v.y; lp[c*4+2] = v.z; lp[c*4+3] = v.w;
            }
            float gp[PVN * 3];
#pragma unroll
            for (int p = 0; p < PVN; p++) {
                float lx = lp[p*3+0], ly = lp[p*3+1], lz = lp[p*3+2];
                gp[p*3+0] = R[0]*lx + R[1]*ly + R[2]*lz + tr[0];
                gp[p*3+1] = R[3]*lx + R[4]*ly + R[5]*lz + tr[1];
                gp[p*3+2] = R[6]*lx + R[7]*ly + R[8]*lz + tr[2];
            }
            float4* dst = reinterpret_cast<float4*>(g_vp + ((long)rt * HPV3 + h * PVN * 3));
#pragma unroll
            for (int c = 0; c < 6; c++)
                dst[c] = make_float4(gp[c*4+0], gp[c*4+1], gp[c*4+2], gp[c*4+3]);
        }
        return;
    }
    int k = idx - KV_TOT;
    if (k >= Q_TOT) return;
    int h = k % HH;
    int row = k / HH;
    int b = row / PROW, i = row % PROW;
    int ridx = b * TT + NPAD + i;
    float R[9], tr[3];
#pragma unroll
    for (int r = 0; r < 9; r++) R[r] = g_r_all[ridx * 9 + r];
#pragma unroll
    for (int r = 0; r < 3; r++) tr[r] = g_t_all[ridx * 3 + r];
    float lp[PQN * 3];
    float4* qp4 = reinterpret_cast<float4*>(g_qp + ((long)row * HPQ3 + h * PQN * 3));
#pragma unroll
    for (int c = 0; c < 3; c++) {
        float4 v = qp4[c];
        lp[c*4+0] = v.x; lp[c*4+1] = v.y; lp[c*4+2] = v.z; lp[c*4+3] = v.w;
    }
    float gp[PQN * 3];
#pragma unroll
    for (int p = 0; p < PQN; p++) {
        float lx = lp[p*3+0], ly = lp[p*3+1], lz = lp[p*3+2];
        gp[p*3+0] = R[0]*lx + R[1]*ly + R[2]*lz + tr[0];
        gp[p*3+1] = R[3]*lx + R[4]*ly + R[5]*lz + tr[1];
        gp[p*3+2] = R[6]*lx + R[7]*ly + R[8]*lz + tr[2];
    }
#pragma unroll
    for (int c = 0; c < 3; c++)
        qp4[c] = make_float4(gp[c*4+0], gp[c*4+1], gp[c*4+2], gp[c*4+3]);
}

// ---------------------------------------------------------------------------
// Split-KV attention (proven config): grid (B*H, PROW/64, ATTS=4), 64 thr.
// ---------------------------------------------------------------------------
#define TJ 32
#define ATH 64
__global__ void attn_split_kernel(const float* __restrict__ gamma) {
    int bh = blockIdx.x;
    int b = bh / HH, h = bh % HH;
    int i = blockIdx.y * ATH + threadIdx.x;
    int sp = blockIdx.z;
    int tid = threadIdx.x;

    int j_begin = sp * ACHUNK;
    int j_end = j_begin + ACHUNK;
    if (j_end > TT) j_end = TT;

    __shared__ __align__(16) float k_s [TJ][CC];
    __shared__ __align__(16) float v_s [TJ][CC];
    __shared__ __align__(16) float kg_s[TJ][PQN * 3];
    __shared__ __align__(16) float vg_s[TJ][PVN * 3];
    __shared__ float sk_s[TJ];

    int qrow = b * PROW + i;
    float q[CC], qg[PQN * 3];
    {
        const float4* q4 = reinterpret_cast<const float4*>(g_q + (long)qrow * HC + h * CC);
#pragma unroll
        for (int c = 0; c < 4; c++) {
            float4 v = q4[c];
            q[c*4+0] = v.x; q[c*4+1] = v.y; q[c*4+2] = v.z; q[c*4+3] = v.w;
        }
        const float4* g4 = reinterpret_cast<const float4*>(g_qp + (long)qrow * HPQ3 + h * PQN * 3);
#pragma unroll
        for (int c = 0; c < 3; c++) {
            float4 v = g4[c];
            qg[c*4+0] = v.x; qg[c*4+1] = v.y; qg[c*4+2] = v.z; qg[c*4+3] = v.w;
        }
    }
    float sq = 0.f;
#pragma unroll
    for (int x = 0; x < PQN * 3; x++) sq += qg[x] * qg[x];

    float gm = gamma[h];
    float gcoef = logf(1.f + __expf(gm)) * WC_HALF;

    float mrun = -1e30f, lrun = 0.f;
    float ao[CC], ag[PVN * 3];
#pragma unroll
    for (int c = 0; c < CC; c++) ao[c] = 0.f;
#pragma unroll
    for (int x = 0; x < PVN * 3; x++) ag[x] = 0.f;

    for (int j0 = j_begin; j0 < j_end; j0 += TJ) {
        __syncthreads();
        for (int x = tid; x < TJ * 4; x += ATH) {
            int j = x >> 2, c4 = x & 3;
            int jj = j0 + j;
            float4 v = (jj < TT)
                ? reinterpret_cast<const float4*>(g_k + ((long)(b * TT + jj) * HC + h * CC))[c4]
                : make_float4(0.f, 0.f, 0.f, 0.f);
            reinterpret_cast<float4*>(&k_s[j][0])[c4] = v;
        }
        for (int x = tid; x < TJ * 4; x += ATH) {
            int j = x >> 2, c4 = x & 3;
            int jj = j0 + j;
            float4 v = (jj < TT)
                ? reinterpret_cast<const float4*>(g_v + ((long)(b * TT + jj) * HC + h * CC))[c4]
                : make_float4(0.f, 0.f, 0.f, 0.f);
            reinterpret_cast<float4*>(&v_s[j][0])[c4] = v;
        }
        for (int x = tid; x < TJ * 3; x += ATH) {
            int j = x / 3, c4 = x % 3;
            int jj = j0 + j;
            float4 v = (jj < TT)
                ? reinterpret_cast<const float4*>(g_kp + ((long)(b * TT + jj) * HPQ3 + h * PQN * 3))[c4]
                : make_float4(0.f, 0.f, 0.f, 0.f);
            reinterpret_cast<float4*>(&kg_s[j][0])[c4] = v;
        }
        for (int x = tid; x < TJ * 6; x += ATH) {
            int j = x / 6, c4 = x % 6;
            int jj = j0 + j;
            float4 v = (jj < TT)
                ? reinterpret_cast<const float4*>(g_vp + ((long)(b * TT + jj) * HPV3 + h * PVN * 3))[c4]
                : make_float4(0.f, 0.f, 0.f, 0.f);
            reinterpret_cast<float4*>(&vg_s[j][0])[c4] = v;
        }
        for (int x = tid; x < TJ; x += ATH) {
            int jj = j0 + x;
            sk_s[x] = (jj < TT) ? g_sk[(long)(b * TT + jj) * HH + h] : 0.f;
        }
        __syncthreads();

        int nv = j_end - j0;
        if (nv > TJ) nv = TJ;

        float logit[TJ];
        float tmax = -1e30f;
#pragma unroll
        for (int jj = 0; jj < TJ; jj++) {
            float qk = 0.f;
            const float4* k4 = reinterpret_cast<const float4*>(&k_s[jj][0]);
#pragma unroll
            for (int c = 0; c < 4; c++) {
                float4 kv = k4[c];
                qk += q[c*4+0] * kv.x + q[c*4+1] * kv.y + q[c*4+2] * kv.z + q[c*4+3] * kv.w;
            }
            float dt = 0.f;
            const float4* g4 = reinterpret_cast<const float4*>(&kg_s[jj][0]);
#pragma unroll
            for (int c = 0; c < 3; c++) {
                float4 kv = g4[c];
                dt += qg[c*4+0] * kv.x + qg[c*4+1] * kv.y + qg[c*4+2] * kv.z + qg[c*4+3] * kv.w;
            }
            float d2 = sq + sk_s[jj] - 2.f * dt;
            float lg = C1 * qk - gcoef * d2;
            logit[jj] = (jj < nv) ? lg : -1e30f;
            tmax = fmaxf(tmax, logit[jj]);
        }
        float mn = fmaxf(mrun, tmax);
        float corr = __expf(mrun - mn);
        lrun *= corr;
#pragma unroll
        for (int c = 0; c < CC; c++) ao[c] *= corr;
#pragma unroll
        for (int x = 0; x < PVN * 3; x++) ag[x] *= corr;
#pragma unroll
        for (int jj = 0; jj < TJ; jj++) {
            float e = __expf(logit[jj] - mn);
            lrun += e;
            const float4* v4 = reinterpret_cast<const float4*>(&v_s[jj][0]);
#pragma unroll
            for (int c = 0; c < 4; c++) {
                float4 vv = v4[c];
                ao[c*4+0] += e * vv.x; ao[c*4+1] += e * vv.y;
                ao[c*4+2] += e * vv.z; ao[c*4+3] += e * vv.w;
            }
            const float4* g4 = reinterpret_cast<const float4*>(&vg_s[jj][0]);
#pragma unroll
            for (int c = 0; c < 6; c++) {
                float4 vv = g4[c];
                ag[c*4+0] += e * vv.x; ag[c*4+1] += e * vv.y;
                ag[c*4+2] += e * vv.z; ag[c*4+3] += e * vv.w;
            }
        }
        mrun = mn;
    }

    int p = (qrow * HH + h) * ATTS + sp;
    g_pm[p] = mrun;
    g_pl[p] = lrun;
#pragma unroll
    for (int c = 0; c < CC; c++) g_po[(long)p * CC + c] = ao[c];
#pragma unroll
    for (int x = 0; x < PVN * 3; x++) g_pg[(long)p * (PVN * 3) + x] = ag[x];
}

// ---------------------------------------------------------------------------
// Combine split partials + build oc rows. One thread per (b,i,h).
// ---------------------------------------------------------------------------
__global__ void combine_oc_kernel() {
    int idx = blockIdx.x * blockDim.x + threadIdx.x;
    if (idx >= BB * PROW * HH) return;
    int h = idx % HH;
    int row = idx / HH;
    int b = row / PROW, i = row % PROW;
    int p0 = idx * ATTS;

    float m = -1e30f;
#pragma unroll
    for (int s = 0; s < ATTS; s++) m = fmaxf(m, g_pm[p0 + s]);
    float L = 0.f;
    float o[CC], g[PVN * 3];
#pragma unroll
    for (int c = 0; c < CC; c++) o[c] = 0.f;
#pragma unroll
    for (int x = 0; x < PVN * 3; x++) g[x] = 0.f;
#pragma unroll
    for (int s = 0; s < ATTS; s++) {
        float w = __expf(g_pm[p0 + s] - m);
        L += g_pl[p0 + s] * w;
        const float* po = g_po + (long)(p0 + s) * CC;
        const float* pg = g_pg + (long)(p0 + s) * (PVN * 3);
#pragma unroll
        for (int c = 0; c < CC; c++) o[c] += w * po[c];
#pragma unroll
        for (int x = 0; x < PVN * 3; x++) g[x] += w * pg[x];
    }
    float inv = 1.f / L;
#pragma unroll
    for (int c = 0; c < CC; c++) o[c] *= inv;
#pragma unroll
    for (int x = 0; x < PVN * 3; x++) g[x] *= inv;

    int ridx = b * TT + NPAD + i;
    float R[9], tr[3];
#pragma unroll
    for (int r = 0; r < 9; r++) R[r] = g_r_all[ridx * 9 + r];
#pragma unroll
    for (int r = 0; r < 3; r++) tr[r] = g_t_all[ridx * 3 + r];

#pragma unroll
    for (int c = 0; c < CC; c++)
        g_oc[(long)row * OCW + h * CC + c] = o[c];

#pragma unroll
    for (int pp = 0; pp < PVN; pp++) {
        float gx = g[pp * 3 + 0] - tr[0];
        float gy = g[pp * 3 + 1] - tr[1];
        float gz = g[pp * 3 + 2] - tr[2];
        float lx = R[0] * gx + R[3] * gy + R[6] * gz;
        float ly = R[1] * gx + R[4] * gy + R[7] * gz;
        float lz = R[2] * gx + R[5] * gy + R[8] * gz;
        g_oc[(long)row * OCW + HC + h * PVN * 3 + pp * 3 + 0] = lx;
        g_oc[(long)row * OCW + HC + h * PVN * 3 + pp * 3 + 1] = ly;
        g_oc[(long)row * OCW + HC + h * PVN * 3 + pp * 3 + 2] = lz;
        g_oc[(long)row * OCW + HC + HPV3 + h * PVN + pp] =
            sqrtf(lx * lx + ly * ly + lz * lz + 1e-8f);
    }
}

// ---------------------------------------------------------------------------
// Finalize: warp per row.
// ---------------------------------------------------------------------------
__global__ void finalize_kernel(const float* __restrict__ bupd,
                                float* __restrict__ out) {
    int gw = (blockIdx.x * blockDim.x + threadIdx.x) >> 5;
    int lane = threadIdx.x & 31;
    if (gw >= BB * PROW) return;
    int row = gw;
    int b = row / PROW, i = row % PROW;
    int ridx = b * TT + NPAD + i;

    float acc[6] = {0.f, 0.f, 0.f, 0.f, 0.f, 0.f};
    const float* ocr = g_oc + (long)row * OCW;
    for (int k = lane; k < OCW; k += 32) {
        float v = ocr[k];
#pragma unroll
        for (int j = 0; j < 6; j++) acc[j] += v * g_wfold[j * OCW + k];
    }
#pragma unroll
    for (int off = 16; off > 0; off >>= 1)
#pragma unroll
        for (int j = 0; j < 6; j++)
            acc[j] += __shfl_down_sync(0xffffffffu, acc[j], off);
    if (lane != 0) return;

    float u[6];
#pragma unroll
    for (int j = 0; j < 6; j++) u[j] = acc[j] + bupd[j];

    float bq = u[0], cq = u[1], dq = u[2];
    float ninv = rsqrtf(1.f + bq * bq + cq * cq + dq * dq);
    float w = ninv, x = bq * ninv, y = cq * ninv, z = dq * ninv;
    float Ru[9];
    Ru[0] = 1.f - 2.f * (y * y + z * z); Ru[1] = 2.f * (x * y - w * z); Ru[2] = 2.f * (x * z + w * y);
    Ru[3] = 2.f * (x * y + w * z); Ru[4] = 1.f - 2.f * (x * x + z * z); Ru[5] = 2.f * (y * z - w * x);
    Ru[6] = 2.f * (x * z - w * y); Ru[7] = 2.f * (y * z + w * x); Ru[8] = 1.f - 2.f * (x * x + y * y);

    float R[9];
#pragma unroll
    for (int r = 0; r < 9; r++) R[r] = g_r_all[ridx * 9 + r];

    float Rn[9];
#pragma unroll
    for (int r = 0; r < 3; r++)
#pragma unroll
        for (int c = 0; c < 3; c++) {
            float a = 0.f;
#pragma unroll
            for (int k = 0; k < 3; k++) a += R[r * 3 + k] * Ru[k * 3 + c];
            Rn[r * 3 + c] = a;
        }

    out[row * 3 + 0] = R[0] * u[3] + R[1] * u[4] + R[2] * u[5] + g_t_all[ridx * 3 + 0];
    out[row * 3 + 1] = R[3] * u[3] + R[4] * u[4] + R[5] * u[5] + g_t_all[ridx * 3 + 1];
    out[row * 3 + 2] = R[6] * u[3] + R[7] * u[4] + R[8] * u[5] + g_t_all[ridx * 3 + 2];
    float* rout = out + BB * PROW * 3;
#pragma unroll
    for (int r = 0; r < 9; r++) rout[row * 9 + r] = Rn[r];
}

// ---------------------------------------------------------------------------
extern "C" void kernel_launch(void* const* d_in, const int* in_sizes, int n_in,
                              void* d_out, int out_size) {
    const float* trans = (const float*)d_in[0];
    const float* rots  = (const float*)d_in[1];
    const float* s     = (const float*)d_in[2];
    const float* wq    = (const float*)d_in[3];
    const float* wk    = (const float*)d_in[4];
    const float* wv    = (const float*)d_in[5];
    const float* wqp   = (const float*)d_in[6];
    const float* wkp   = (const float*)d_in[7];
    const float* wvp   = (const float*)d_in[8];
    const float* gamma = (const float*)d_in[9];
    const float* wout  = (const float*)d_in[10];
    const float* wupd  = (const float*)d_in[11];
    const float* bupd  = (const float*)d_in[12];
    float* out = (float*)d_out;

    float *p_s_pool, *p_k0, *p_v0, *p_kp0, *p_vp0, *p_q, *p_qp;
    cudaGetSymbolAddress((void**)&p_s_pool, g_s_pool);
    cudaGetSymbolAddress((void**)&p_k0, g_k0);
    cudaGetSymbolAddress((void**)&p_v0, g_v0);
    cudaGetSymbolAddress((void**)&p_kp0, g_kp0);
    cudaGetSymbolAddress((void**)&p_vp0, g_vp0);
    cudaGetSymbolAddress((void**)&p_q, g_q);
    cudaGetSymbolAddress((void**)&p_qp, g_qp);

    // 1. prep: pooled s rows + t/r expansion
    prep_all_kernel<<<(SP_TOT + TR_TOT + 255) / 256, 256>>>(s, trans, rots);

    // 2. projection GEMMs on RAW s rows (2048) + pooled rows (1024) for q
    TaskPack P;
    int Mraw = BB * NN;     // 2048
    int Mpool = BB * PROW;  // 1024
    auto setTask = [&](int ti, const float* A, const float* B, float* C,
                       int M, int N, int K) {
        P.t[ti].A = A; P.t[ti].B = B; P.t[ti].C = C;
        P.t[ti].M = M; P.t[ti].N = N; P.t[ti].K = K;
        P.t[ti].gx = (N + GBN - 1) / GBN;
    };
    setTask(0, s, wk,  p_k0,  Mraw, HC,   CSD);
    setTask(1, s, wv,  p_v0,  Mraw, HC,   CSD);
    setTask(2, s, wkp, p_kp0, Mraw, HPQ3, CSD);
    setTask(3, s, wvp, p_vp0, Mraw, HPV3, CSD);
    setTask(4, p_s_pool, wq,  p_q,  Mpool, HC,   CSD);
    setTask(5, p_s_pool, wqp, p_qp, Mpool, HPQ3, CSD);
    P.ofs[0] = 0;
    for (int ti = 0; ti < NTASK; ti++) {
        int gy = (P.t[ti].M + GBM - 1) / GBM;
        P.ofs[ti + 1] = P.ofs[ti] + P.t[ti].gx * gy;
    }
    mgemm_kernel<<<P.ofs[NTASK], 256>>>(P);

    // 3. weight fold
    fold_w_kernel<<<(OCW * 32 + 255) / 256, 256>>>(wout, wupd);

    // 4. expand to TT rows + point transforms (fused)
    expand_transform_kernel<<<(KV_TOT + Q_TOT + 255) / 256, 256>>>();

    // 5. split-KV attention
    attn_split_kernel<<<dim3(BB * HH, PROW / ATH, ATTS), ATH>>>(gamma);

    // 6. combine + build oc
    combine_oc_kernel<<<(BB * PROW * HH + 255) / 256, 256>>>();

    // 7. finalize
    finalize_kernel<<<(BB * PROW * 32 + 255) / 256, 256>>>(bupd, out);
}